// round 14
// baseline (speedup 1.0000x reference)
#include <cuda_runtime.h>
#include <math_constants.h>

// Problem constants
#define N_BATCH 4
#define C_CH    128
#define S_FR    31
#define HW      704           // 32*22
#define NS      120           // 4*(31-1)
#define NPIX    87296         // 4*31*704 (= 64*1364)
#define TOPK    16
#define NB      64            // denominator bins
#define LOG2E   1.4426950408889634f
#define LN2F    0.6931471805599453f

// Scratch (device globals — no allocation allowed)
__device__ float  g_X0[NS * HW];        // a values
__device__ float  g_BL[NS * HW];        // b * log2e (order-preserving)
__device__ float  g_TB[NS * 32];        // [0..15] top desc, [16..31] bottom asc
__device__ float4 g_BINS[NS * NB];      // (S0, S1, S2/2, S3/6)
__device__ float2 g_ROW[NS];            // (lo, W)
__device__ int    g_FLAG[NS];           // summary-done flags (reset by kA)

__device__ __forceinline__ float ex2(float x) {
    float r;
    asm("ex2.approx.f32 %0, %1;" : "=f"(r) : "f"(x));
    return r;
}

// ---------------------------------------------------------------------------
// Kernel A (R3 winner): channel contraction, 2 threads per pixel.
// Block 0 additionally resets the per-row flags (stream-ordered before kD).
// ---------------------------------------------------------------------------
__global__ void kA(const float* __restrict__ x,
                   const float* __restrict__ w1, const float* __restrict__ b1,
                   const float* __restrict__ w2, const float* __restrict__ b2) {
    __shared__ float sw1[C_CH], sw2[C_CH];
    __shared__ float r1s[64], r2s[64];
    int tid = threadIdx.x;          // 0..127
    if (blockIdx.x == 0 && tid < NS) g_FLAG[tid] = 0;
    sw1[tid] = w1[tid];
    sw2[tid] = w2[tid];
    __syncthreads();

    int half = tid >> 6;            // 0 or 1
    int px   = tid & 63;
    int p = blockIdx.x * 64 + px;   // NPIX = 64*1364 exactly
    int n = p / (S_FR * HW);
    int q = p - n * (S_FR * HW);
    int f = q / HW;
    int i = q - f * HW;

    const float* xp = x + (size_t)n * (C_CH * S_FR * HW)
                        + (size_t)(half * 64) * (S_FR * HW) + q;
    const float* pw1 = sw1 + half * 64;
    const float* pw2 = sw2 + half * 64;

    float y1a = 0.f, y1b = 0.f, y2a = 0.f, y2b = 0.f;
#pragma unroll
    for (int cb = 0; cb < 64; cb += 16) {
        float v[16];
#pragma unroll
        for (int u = 0; u < 16; u++) v[u] = xp[(cb + u) * (S_FR * HW)];
#pragma unroll
        for (int u = 0; u < 16; u += 2) {
            y1a = fmaf(v[u],     pw1[cb + u],     y1a);
            y2a = fmaf(v[u],     pw2[cb + u],     y2a);
            y1b = fmaf(v[u + 1], pw1[cb + u + 1], y1b);
            y2b = fmaf(v[u + 1], pw2[cb + u + 1], y2b);
        }
    }
    float y1 = y1a + y1b, y2 = y2a + y2b;

    if (half == 1) { r1s[px] = y1; r2s[px] = y2; }
    __syncthreads();
    if (half == 0) {
        y1 += r1s[px];
        y2 += r2s[px];
        if (f < S_FR - 1) g_X0[(n * (S_FR - 1) + f) * HW + i] = y1 + b1[0];
        if (f >= 1)       g_BL[(n * (S_FR - 1) + f - 1) * HW + i] = (y2 + b2[0]) * LOG2E;
    }
}

// ---------------------------------------------------------------------------
// Kernel D: fused summary + emit with intra-kernel flag handoff.
// Blocks 0..119: per-row summary -> g_TB/g_BINS/g_ROW -> release flag.
// Blocks 120..1439: emit (11 x 64-pixel chunks per row); spin on flag.
// 1440 blocks x 64 threads: all co-resident (10 blocks/SM) -> spin is safe.
// ---------------------------------------------------------------------------
__global__ void __launch_bounds__(64)
kD(float* __restrict__ out) {
    int b   = blockIdx.x;
    int tid = threadIdx.x;   // 0..63
    int lane = tid & 31, wid = tid >> 5;

    if (b < NS) {
        // ================= summary block for row r = b =================
        __shared__ float sv[HW], sv2[HW];
        __shared__ float binS0[NB], binS1[NB], binS2[NB], binS3[NB];
        __shared__ float s_mm[4];
        __shared__ float s_lo, s_W;
        __shared__ int   s_ttop, s_tbot, s_fbtop, s_fbbot, s_ctop, s_cbot;
        __shared__ float candT[40], candB[40];
        int r = b;

        float v[11]; int mb[11];
#pragma unroll
        for (int j = 0; j < 11; j++) {
            float t = g_BL[r * HW + j * 64 + tid];
            v[j] = t; sv[j * 64 + tid] = t; sv2[j * 64 + tid] = t;
        }
        binS0[tid] = 0.f; binS1[tid] = 0.f; binS2[tid] = 0.f; binS3[tid] = 0.f;
        if (tid == 0) { s_ctop = 0; s_cbot = 0; }

        float lmin = v[0], lmax = v[0];
#pragma unroll
        for (int j = 1; j < 11; j++) { lmin = fminf(lmin, v[j]); lmax = fmaxf(lmax, v[j]); }
#pragma unroll
        for (int o = 16; o; o >>= 1) {
            lmin = fminf(lmin, __shfl_xor_sync(0xffffffffu, lmin, o));
            lmax = fmaxf(lmax, __shfl_xor_sync(0xffffffffu, lmax, o));
        }
        if (lane == 0) { s_mm[wid] = lmin; s_mm[2 + wid] = lmax; }
        __syncthreads();
        if (tid == 0) {
            float lo = fminf(s_mm[0], s_mm[1]);
            float hi = fmaxf(s_mm[2], s_mm[3]);
            s_lo = lo;
            s_W  = (hi - lo) * (1.0f / NB) + 1e-30f;
            g_ROW[r] = make_float2(lo, s_W);
        }
        __syncthreads();

        float lo = s_lo, W = s_W, invW = 1.0f / W;
#pragma unroll
        for (int j = 0; j < 11; j++) {
            int m = (int)((v[j] - lo) * invW);
            m = (m > NB - 1) ? NB - 1 : (m < 0 ? 0 : m);
            mb[j] = m;
            float d = v[j] - fmaf((float)m + 0.5f, W, lo);
            atomicAdd(&binS0[m], 1.0f);
            atomicAdd(&binS1[m], d);
            atomicAdd(&binS2[m], 0.5f * d * d);
            atomicAdd(&binS3[m], (1.0f / 6.0f) * d * d * d);
        }
        __syncthreads();

        // thresholds (lane owns bins 2l, 2l+1)
        if (wid == 0) {
            float c0 = binS0[2 * lane];
            float c1 = binS0[2 * lane + 1];
            float suf = c0 + c1;
#pragma unroll
            for (int o = 1; o < 32; o <<= 1) {
                float t = __shfl_down_sync(0xffffffffu, suf, o);
                if (lane + o < 32) suf += t;
            }
            float Seven = suf;              // suffix from bin 2l
            float Sodd  = suf - c0;         // suffix from bin 2l+1
            int best = -1;
            if (Sodd  >= 16.f) best = 2 * lane + 1;
            else if (Seven >= 16.f) best = 2 * lane;
            float Sb = (best == 2 * lane + 1) ? Sodd : ((best == 2 * lane) ? Seven : 0.f);
#pragma unroll
            for (int o = 16; o; o >>= 1) {
                int   ob = __shfl_xor_sync(0xffffffffu, best, o);
                float os = __shfl_xor_sync(0xffffffffu, Sb, o);
                if (ob > best) { best = ob; Sb = os; }
            }
            if (lane == 0) { s_ttop = best; s_fbtop = (Sb > 32.f) ? 1 : 0; }
        } else {
            float c0 = binS0[2 * lane];
            float c1 = binS0[2 * lane + 1];
            float pre = c0 + c1;
#pragma unroll
            for (int o = 1; o < 32; o <<= 1) {
                float t = __shfl_up_sync(0xffffffffu, pre, o);
                if (lane >= o) pre += t;
            }
            float Podd  = pre;              // prefix through 2l+1
            float Peven = pre - c1;         // prefix through 2l
            int best = 0x7fffffff;
            if (Peven >= 16.f) best = 2 * lane;
            else if (Podd >= 16.f) best = 2 * lane + 1;
            float Pb = (best == 2 * lane) ? Peven : ((best == 2 * lane + 1) ? Podd : 0.f);
#pragma unroll
            for (int o = 16; o; o >>= 1) {
                int   ob = __shfl_xor_sync(0xffffffffu, best, o);
                float os = __shfl_xor_sync(0xffffffffu, Pb, o);
                if (ob < best) { best = ob; Pb = os; }
            }
            if (lane == 0) { s_tbot = best; s_fbbot = (Pb > 32.f) ? 1 : 0; }
        }
        __syncthreads();

        // candidate gather + bins writeout (tid < 64 == NB)
        if (!s_fbtop) {
#pragma unroll
            for (int j = 0; j < 11; j++)
                if (mb[j] >= s_ttop) candT[atomicAdd(&s_ctop, 1)] = v[j];
        }
        if (!s_fbbot) {
#pragma unroll
            for (int j = 0; j < 11; j++)
                if (mb[j] <= s_tbot) candB[atomicAdd(&s_cbot, 1)] = v[j];
        }
        g_BINS[r * NB + tid] = make_float4(binS0[tid], binS1[tid], binS2[tid], binS3[tid]);
        __syncthreads();

        // selection: warp 0 top-16 desc, warp 1 bottom-16 asc
        if (wid == 0) {
            if (!s_fbtop) {
                float vv = (lane < s_ctop) ? candT[lane] : -CUDART_INF_F;
#pragma unroll
                for (int k = 2; k <= 32; k <<= 1) {
#pragma unroll
                    for (int j = k >> 1; j > 0; j >>= 1) {
                        float o = __shfl_xor_sync(0xffffffffu, vv, j);
                        bool up = ((lane & k) == 0);
                        bool keepMin = (((lane & j) == 0) == up);
                        vv = keepMin ? fminf(vv, o) : fmaxf(vv, o);
                    }
                }
                if (lane >= 16) g_TB[r * 32 + (31 - lane)] = vv;
            } else {
                for (int it = 0; it < TOPK; it++) {
                    float lm = -CUDART_INF_F; int li = 0;
                    for (int j = lane; j < HW; j += 32) {
                        float t = sv[j];
                        if (t > lm) { lm = t; li = j; }
                    }
#pragma unroll
                    for (int o = 16; o; o >>= 1) {
                        float ov = __shfl_xor_sync(0xffffffffu, lm, o);
                        int   oi = __shfl_xor_sync(0xffffffffu, li, o);
                        if (ov > lm || (ov == lm && oi < li)) { lm = ov; li = oi; }
                    }
                    if (lane == 0) { g_TB[r * 32 + it] = lm; sv[li] = -CUDART_INF_F; }
                    __syncwarp();
                }
            }
        } else {
            if (!s_fbbot) {
                float vv = (lane < s_cbot) ? candB[lane] : CUDART_INF_F;
#pragma unroll
                for (int k = 2; k <= 32; k <<= 1) {
#pragma unroll
                    for (int j = k >> 1; j > 0; j >>= 1) {
                        float o = __shfl_xor_sync(0xffffffffu, vv, j);
                        bool up = ((lane & k) == 0);
                        bool keepMin = (((lane & j) == 0) == up);
                        vv = keepMin ? fminf(vv, o) : fmaxf(vv, o);
                    }
                }
                if (lane < 16) g_TB[r * 32 + 16 + lane] = vv;
            } else {
                for (int it = 0; it < TOPK; it++) {
                    float lm = CUDART_INF_F; int li = 0;
                    for (int j = lane; j < HW; j += 32) {
                        float t = sv2[j];
                        if (t < lm) { lm = t; li = j; }
                    }
#pragma unroll
                    for (int o = 16; o; o >>= 1) {
                        float ov = __shfl_xor_sync(0xffffffffu, lm, o);
                        int   oi = __shfl_xor_sync(0xffffffffu, li, o);
                        if (ov < lm || (ov == lm && oi < li)) { lm = ov; li = oi; }
                    }
                    if (lane == 0) { g_TB[r * 32 + 16 + it] = lm; sv2[li] = CUDART_INF_F; }
                    __syncwarp();
                }
            }
        }

        // release: all data written -> fence -> flag
        __threadfence();
        __syncthreads();
        if (tid == 0) atomicExch(&g_FLAG[r], 1);

    } else {
        // ================= emit block =================
        __shared__ float4 sb[NB];
        __shared__ float  ssel[32];
        __shared__ float2 srow;
        int e = b - NS;
        int r = e / 11;
        int chunk = e - r * 11;
        int i = chunk * 64 + tid;

        float a = g_X0[r * HW + i];   // independent of flag (written by kA)

        if (tid == 0) {
            while (((volatile int*)g_FLAG)[r] == 0) __nanosleep(64);
            __threadfence();
        }
        __syncthreads();

        sb[tid] = g_BINS[r * NB + tid];
        if (tid < 32) ssel[tid] = g_TB[r * 32 + tid];
        if (tid == 63) srow = g_ROW[r];
        __syncthreads();

        float lo = srow.x, W = srow.y;
        bool  pos  = (a >= 0.f);
        float u    = a * W;
        float mref = pos ? (float)(NB - 1) : 0.f;
        float cs   = fmaf(mref + 0.5f, W, lo);     // dominant bin center
        float L    = a * LN2F;
        float g1   = ex2(u);
        float g2   = g1 * g1;
        float g3   = g2 * g1;
        float g4   = g2 * g2;

        float D0 = 0.f, D1 = 0.f, D2 = 0.f, D3 = 0.f;
#pragma unroll
        for (int grp = 0; grp < NB; grp += 8) {
            float pr = ex2(u * ((float)grp - mref));
            float q0 = pr, q1 = pr * g1, q2 = pr * g2, q3 = pr * g3;
            float4 c0 = sb[grp + 0];
            float4 c1 = sb[grp + 1];
            float4 c2 = sb[grp + 2];
            float4 c3 = sb[grp + 3];
            D0 = fmaf(q0, fmaf(L, fmaf(L, fmaf(L, c0.w, c0.z), c0.y), c0.x), D0);
            D1 = fmaf(q1, fmaf(L, fmaf(L, fmaf(L, c1.w, c1.z), c1.y), c1.x), D1);
            D2 = fmaf(q2, fmaf(L, fmaf(L, fmaf(L, c2.w, c2.z), c2.y), c2.x), D2);
            D3 = fmaf(q3, fmaf(L, fmaf(L, fmaf(L, c3.w, c3.z), c3.y), c3.x), D3);
            q0 *= g4; q1 *= g4; q2 *= g4; q3 *= g4;
            float4 c4 = sb[grp + 4];
            float4 c5 = sb[grp + 5];
            float4 c6 = sb[grp + 6];
            float4 c7 = sb[grp + 7];
            D0 = fmaf(q0, fmaf(L, fmaf(L, fmaf(L, c4.w, c4.z), c4.y), c4.x), D0);
            D1 = fmaf(q1, fmaf(L, fmaf(L, fmaf(L, c5.w, c5.z), c5.y), c5.x), D1);
            D2 = fmaf(q2, fmaf(L, fmaf(L, fmaf(L, c6.w, c6.z), c6.y), c6.x), D2);
            D3 = fmaf(q3, fmaf(L, fmaf(L, fmaf(L, c7.w, c7.z), c7.y), c7.x), D3);
        }
        float Dref = (D0 + D1) + (D2 + D3);   // = sum exp2(a*bl_j - a*cs)

        float nm = -a * cs;
        float rD = __frcp_rn(Dref);
        const float* sel = pos ? ssel : (ssel + 16);
        float vv[TOPK];
#pragma unroll
        for (int k = 0; k < TOPK; k++)
            vv[k] = ex2(fmaf(a, sel[k], nm)) * rD;

        // output: idx = i*16 + k ; k2 = i/44 (k-independent)
        int n  = r / (S_FR - 1);
        int sp = r - n * (S_FR - 1);
        int k2 = i / 44;
        int im = i - k2 * 44;
        float4* o = reinterpret_cast<float4*>(
            out + ((size_t)((n * TOPK + k2) * (S_FR - 1) + sp)) * HW + im * 16);
        o[0] = make_float4(vv[0],  vv[1],  vv[2],  vv[3]);
        o[1] = make_float4(vv[4],  vv[5],  vv[6],  vv[7]);
        o[2] = make_float4(vv[8],  vv[9],  vv[10], vv[11]);
        o[3] = make_float4(vv[12], vv[13], vv[14], vv[15]);
    }
}

// ---------------------------------------------------------------------------
extern "C" void kernel_launch(void* const* d_in, const int* in_sizes, int n_in,
                              void* d_out, int out_size) {
    const float* x  = (const float*)d_in[0];
    const float* w1 = (const float*)d_in[1];
    const float* b1 = (const float*)d_in[2];
    const float* w2 = (const float*)d_in[3];
    const float* b2 = (const float*)d_in[4];
    float* out = (float*)d_out;

    kA<<<NPIX / 64, 128>>>(x, w1, b1, w2, b2);
    kD<<<NS * 12, 64>>>(out);
}

// round 15
// speedup vs baseline: 1.1181x; 1.1181x over previous
#include <cuda_runtime.h>
#include <math_constants.h>

// Problem constants
#define N_BATCH 4
#define C_CH    128
#define S_FR    31
#define HW      704           // 32*22
#define NS      120           // 4*(31-1)
#define NPIX    87296         // 4*31*704 (= 64*1364)
#define TOPK    16
#define NB      64            // denominator bins
#define LOG2E   1.4426950408889634f
#define LN2F    0.6931471805599453f

// Scratch (device globals — no allocation allowed)
__device__ float  g_X0[NS * HW];        // a values
__device__ float  g_BL[NS * HW];        // b * log2e (order-preserving)
__device__ float  g_TB[NS * 32];        // [0..15] top desc, [16..31] bottom asc
__device__ float4 g_BINS[NS * NB];      // (S0, S1, S2/2, S3/6)
__device__ float2 g_ROW[NS];            // (lo, W)
__device__ int    g_CNT[NS];            // zero-init; finisher resets to 0

__device__ __forceinline__ float ex2(float x) {
    float r;
    asm("ex2.approx.f32 %0, %1;" : "=f"(r) : "f"(x));
    return r;
}

// ---------------------------------------------------------------------------
// Kernel A: channel contraction (R3 mainloop) + last-block-wins row summary.
// 1364 blocks x 128 threads; each block covers 64 pixels of one (n, f).
// The 11th block to complete a row's BL runs that row's summary inline.
// ---------------------------------------------------------------------------
__global__ void __launch_bounds__(128)
kA(const float* __restrict__ x,
   const float* __restrict__ w1, const float* __restrict__ b1,
   const float* __restrict__ w2, const float* __restrict__ b2) {
    __shared__ float sw1[C_CH], sw2[C_CH];
    __shared__ float r1s[64], r2s[64];
    // summary smem (used only by finisher path)
    __shared__ float sv[HW], sv2[HW];
    __shared__ float binS0[NB], binS1[NB], binS2[NB], binS3[NB];
    __shared__ float s_mm[8];
    __shared__ float s_lo, s_W;
    __shared__ int   s_old, s_ttop, s_tbot, s_fbtop, s_fbbot, s_ctop, s_cbot;
    __shared__ float candT[40], candB[40];

    int tid = threadIdx.x;          // 0..127
    int lane = tid & 31, wid = tid >> 5;
    sw1[tid] = w1[tid];
    sw2[tid] = w2[tid];
    __syncthreads();

    int half = tid >> 6;            // 0 or 1
    int px   = tid & 63;
    int p = blockIdx.x * 64 + px;   // NPIX = 64*1364 exactly
    int n = p / (S_FR * HW);
    int q = p - n * (S_FR * HW);
    int f = q / HW;                 // block never straddles n or f
    int i = q - f * HW;

    const float* xp = x + (size_t)n * (C_CH * S_FR * HW)
                        + (size_t)(half * 64) * (S_FR * HW) + q;
    const float* pw1 = sw1 + half * 64;
    const float* pw2 = sw2 + half * 64;

    float y1a = 0.f, y1b = 0.f, y2a = 0.f, y2b = 0.f;
#pragma unroll
    for (int cb = 0; cb < 64; cb += 16) {
        float v[16];
#pragma unroll
        for (int u = 0; u < 16; u++) v[u] = xp[(cb + u) * (S_FR * HW)];
#pragma unroll
        for (int u = 0; u < 16; u += 2) {
            y1a = fmaf(v[u],     pw1[cb + u],     y1a);
            y2a = fmaf(v[u],     pw2[cb + u],     y2a);
            y1b = fmaf(v[u + 1], pw1[cb + u + 1], y1b);
            y2b = fmaf(v[u + 1], pw2[cb + u + 1], y2b);
        }
    }
    float y1 = y1a + y1b, y2 = y2a + y2b;

    if (half == 1) { r1s[px] = y1; r2s[px] = y2; }
    __syncthreads();
    if (half == 0) {
        y1 += r1s[px];
        y2 += r2s[px];
        if (f < S_FR - 1) g_X0[(n * (S_FR - 1) + f) * HW + i] = y1 + b1[0];
        if (f >= 1)       g_BL[(n * (S_FR - 1) + f - 1) * HW + i] = (y2 + b2[0]) * LOG2E;
        __threadfence();            // release our BL stores
    }

    if (f < 1) return;              // no row produced by this block
    int r = n * (S_FR - 1) + f - 1;

    __syncthreads();                // all writers fenced before arrival
    if (tid == 0) s_old = atomicAdd(&g_CNT[r], 1);
    __syncthreads();
    if (s_old != 10) return;        // not the finisher

    // ================= finisher: row summary (128 threads) =================
    __threadfence();                // acquire
    if (tid == 0) g_CNT[r] = 0;     // reset for next graph replay

    float v6[6]; int mb6[6];
#pragma unroll
    for (int j = 0; j < 6; j++) {
        int idx = tid + j * 128;
        float t = (idx < HW) ? __ldcg(&g_BL[r * HW + idx]) : 0.f;
        v6[j] = t;
        if (idx < HW) { sv[idx] = t; sv2[idx] = t; }
    }
    if (tid < NB) { binS0[tid] = 0.f; binS1[tid] = 0.f; binS2[tid] = 0.f; binS3[tid] = 0.f; }
    if (tid == 0) { s_ctop = 0; s_cbot = 0; }

    int nval = (tid < 64) ? 6 : 5;
    float lmin = v6[0], lmax = v6[0];
#pragma unroll
    for (int j = 1; j < 6; j++) {
        if (j < nval) { lmin = fminf(lmin, v6[j]); lmax = fmaxf(lmax, v6[j]); }
    }
#pragma unroll
    for (int o = 16; o; o >>= 1) {
        lmin = fminf(lmin, __shfl_xor_sync(0xffffffffu, lmin, o));
        lmax = fmaxf(lmax, __shfl_xor_sync(0xffffffffu, lmax, o));
    }
    if (lane == 0) { s_mm[wid] = lmin; s_mm[4 + wid] = lmax; }
    __syncthreads();
    if (tid == 0) {
        float lo = fminf(fminf(s_mm[0], s_mm[1]), fminf(s_mm[2], s_mm[3]));
        float hi = fmaxf(fmaxf(s_mm[4], s_mm[5]), fmaxf(s_mm[6], s_mm[7]));
        s_lo = lo;
        s_W  = (hi - lo) * (1.0f / NB) + 1e-30f;
        g_ROW[r] = make_float2(lo, s_W);
    }
    __syncthreads();

    float lo = s_lo, W = s_W, invW = 1.0f / W;
#pragma unroll
    for (int j = 0; j < 6; j++) {
        if (j < nval) {
            int m = (int)((v6[j] - lo) * invW);
            m = (m > NB - 1) ? NB - 1 : (m < 0 ? 0 : m);
            mb6[j] = m;
            float d = v6[j] - fmaf((float)m + 0.5f, W, lo);
            atomicAdd(&binS0[m], 1.0f);
            atomicAdd(&binS1[m], d);
            atomicAdd(&binS2[m], 0.5f * d * d);
            atomicAdd(&binS3[m], (1.0f / 6.0f) * d * d * d);
        } else mb6[j] = -1000000;
    }
    __syncthreads();

    // thresholds (lane owns bins 2l, 2l+1)
    if (wid == 0) {
        float c0 = binS0[2 * lane];
        float c1 = binS0[2 * lane + 1];
        float suf = c0 + c1;
#pragma unroll
        for (int o = 1; o < 32; o <<= 1) {
            float t = __shfl_down_sync(0xffffffffu, suf, o);
            if (lane + o < 32) suf += t;
        }
        float Seven = suf;              // suffix from bin 2l
        float Sodd  = suf - c0;         // suffix from bin 2l+1
        int best = -1;
        if (Sodd  >= 16.f) best = 2 * lane + 1;
        else if (Seven >= 16.f) best = 2 * lane;
        float Sb = (best == 2 * lane + 1) ? Sodd : ((best == 2 * lane) ? Seven : 0.f);
#pragma unroll
        for (int o = 16; o; o >>= 1) {
            int   ob = __shfl_xor_sync(0xffffffffu, best, o);
            float os = __shfl_xor_sync(0xffffffffu, Sb, o);
            if (ob > best) { best = ob; Sb = os; }
        }
        if (lane == 0) { s_ttop = best; s_fbtop = (Sb > 32.f) ? 1 : 0; }
    } else if (wid == 1) {
        float c0 = binS0[2 * lane];
        float c1 = binS0[2 * lane + 1];
        float pre = c0 + c1;
#pragma unroll
        for (int o = 1; o < 32; o <<= 1) {
            float t = __shfl_up_sync(0xffffffffu, pre, o);
            if (lane >= o) pre += t;
        }
        float Podd  = pre;              // prefix through 2l+1
        float Peven = pre - c1;         // prefix through 2l
        int best = 0x7fffffff;
        if (Peven >= 16.f) best = 2 * lane;
        else if (Podd >= 16.f) best = 2 * lane + 1;
        float Pb = (best == 2 * lane) ? Peven : ((best == 2 * lane + 1) ? Podd : 0.f);
#pragma unroll
        for (int o = 16; o; o >>= 1) {
            int   ob = __shfl_xor_sync(0xffffffffu, best, o);
            float os = __shfl_xor_sync(0xffffffffu, Pb, o);
            if (ob < best) { best = ob; Pb = os; }
        }
        if (lane == 0) { s_tbot = best; s_fbbot = (Pb > 32.f) ? 1 : 0; }
    }
    __syncthreads();

    // candidate gather + bins writeout
    if (!s_fbtop) {
#pragma unroll
        for (int j = 0; j < 6; j++)
            if (mb6[j] >= s_ttop) candT[atomicAdd(&s_ctop, 1)] = v6[j];
    }
    if (!s_fbbot) {
#pragma unroll
        for (int j = 0; j < 6; j++)
            if (mb6[j] >= 0 && mb6[j] <= s_tbot) candB[atomicAdd(&s_cbot, 1)] = v6[j];
    }
    if (tid < NB)
        g_BINS[r * NB + tid] = make_float4(binS0[tid], binS1[tid], binS2[tid], binS3[tid]);
    __syncthreads();

    // selection: warp 0 top-16 desc, warp 1 bottom-16 asc
    if (wid == 0) {
        if (!s_fbtop) {
            float vv = (lane < s_ctop) ? candT[lane] : -CUDART_INF_F;
#pragma unroll
            for (int k = 2; k <= 32; k <<= 1) {
#pragma unroll
                for (int j = k >> 1; j > 0; j >>= 1) {
                    float o = __shfl_xor_sync(0xffffffffu, vv, j);
                    bool up = ((lane & k) == 0);
                    bool keepMin = (((lane & j) == 0) == up);
                    vv = keepMin ? fminf(vv, o) : fmaxf(vv, o);
                }
            }
            if (lane >= 16) g_TB[r * 32 + (31 - lane)] = vv;
        } else {
            for (int it = 0; it < TOPK; it++) {
                float lm = -CUDART_INF_F; int li = 0;
                for (int j = lane; j < HW; j += 32) {
                    float t = sv[j];
                    if (t > lm) { lm = t; li = j; }
                }
#pragma unroll
                for (int o = 16; o; o >>= 1) {
                    float ov = __shfl_xor_sync(0xffffffffu, lm, o);
                    int   oi = __shfl_xor_sync(0xffffffffu, li, o);
                    if (ov > lm || (ov == lm && oi < li)) { lm = ov; li = oi; }
                }
                if (lane == 0) { g_TB[r * 32 + it] = lm; sv[li] = -CUDART_INF_F; }
                __syncwarp();
            }
        }
    } else if (wid == 1) {
        if (!s_fbbot) {
            float vv = (lane < s_cbot) ? candB[lane] : CUDART_INF_F;
#pragma unroll
            for (int k = 2; k <= 32; k <<= 1) {
#pragma unroll
                for (int j = k >> 1; j > 0; j >>= 1) {
                    float o = __shfl_xor_sync(0xffffffffu, vv, j);
                    bool up = ((lane & k) == 0);
                    bool keepMin = (((lane & j) == 0) == up);
                    vv = keepMin ? fminf(vv, o) : fmaxf(vv, o);
                }
            }
            if (lane < 16) g_TB[r * 32 + 16 + lane] = vv;
        } else {
            for (int it = 0; it < TOPK; it++) {
                float lm = CUDART_INF_F; int li = 0;
                for (int j = lane; j < HW; j += 32) {
                    float t = sv2[j];
                    if (t < lm) { lm = t; li = j; }
                }
#pragma unroll
                for (int o = 16; o; o >>= 1) {
                    float ov = __shfl_xor_sync(0xffffffffu, lm, o);
                    int   oi = __shfl_xor_sync(0xffffffffu, li, o);
                    if (ov < lm || (ov == lm && oi < li)) { lm = ov; li = oi; }
                }
                if (lane == 0) { g_TB[r * 32 + 16 + it] = lm; sv2[li] = CUDART_INF_F; }
                __syncwarp();
            }
        }
    }
}

// ---------------------------------------------------------------------------
// Kernel C (R10, verbatim): wide barrier-free emit. 1320 blocks x 64 threads.
// ---------------------------------------------------------------------------
__global__ void __launch_bounds__(64)
kC(float* __restrict__ out) {
    __shared__ float4 sb[NB];
    __shared__ float  ssel[32];
    __shared__ float2 srow;
    int r = blockIdx.x / 11;
    int chunk = blockIdx.x - r * 11;
    int tid = threadIdx.x;   // 64

    sb[tid] = g_BINS[r * NB + tid];
    if (tid < 32) ssel[tid] = g_TB[r * 32 + tid];
    if (tid == 63) srow = g_ROW[r];
    __syncthreads();

    int i = chunk * 64 + tid;
    float a  = g_X0[r * HW + i];
    float lo = srow.x, W = srow.y;

    bool  pos  = (a >= 0.f);
    float u    = a * W;
    float mref = pos ? (float)(NB - 1) : 0.f;
    float cs   = fmaf(mref + 0.5f, W, lo);     // dominant bin center
    float L    = a * LN2F;
    float g1   = ex2(u);
    float g2   = g1 * g1;
    float g3   = g2 * g1;
    float g4   = g2 * g2;

    float D0 = 0.f, D1 = 0.f, D2 = 0.f, D3 = 0.f;
#pragma unroll
    for (int grp = 0; grp < NB; grp += 8) {
        float pr = ex2(u * ((float)grp - mref));
        float q0 = pr, q1 = pr * g1, q2 = pr * g2, q3 = pr * g3;
        float4 c0 = sb[grp + 0];
        float4 c1 = sb[grp + 1];
        float4 c2 = sb[grp + 2];
        float4 c3 = sb[grp + 3];
        D0 = fmaf(q0, fmaf(L, fmaf(L, fmaf(L, c0.w, c0.z), c0.y), c0.x), D0);
        D1 = fmaf(q1, fmaf(L, fmaf(L, fmaf(L, c1.w, c1.z), c1.y), c1.x), D1);
        D2 = fmaf(q2, fmaf(L, fmaf(L, fmaf(L, c2.w, c2.z), c2.y), c2.x), D2);
        D3 = fmaf(q3, fmaf(L, fmaf(L, fmaf(L, c3.w, c3.z), c3.y), c3.x), D3);
        q0 *= g4; q1 *= g4; q2 *= g4; q3 *= g4;
        float4 c4 = sb[grp + 4];
        float4 c5 = sb[grp + 5];
        float4 c6 = sb[grp + 6];
        float4 c7 = sb[grp + 7];
        D0 = fmaf(q0, fmaf(L, fmaf(L, fmaf(L, c4.w, c4.z), c4.y), c4.x), D0);
        D1 = fmaf(q1, fmaf(L, fmaf(L, fmaf(L, c5.w, c5.z), c5.y), c5.x), D1);
        D2 = fmaf(q2, fmaf(L, fmaf(L, fmaf(L, c6.w, c6.z), c6.y), c6.x), D2);
        D3 = fmaf(q3, fmaf(L, fmaf(L, fmaf(L, c7.w, c7.z), c7.y), c7.x), D3);
    }
    float Dref = (D0 + D1) + (D2 + D3);   // = sum exp2(a*bl_j - a*cs)

    float nm = -a * cs;
    float rD = __frcp_rn(Dref);
    const float* sel = pos ? ssel : (ssel + 16);
    float v[TOPK];
#pragma unroll
    for (int k = 0; k < TOPK; k++)
        v[k] = ex2(fmaf(a, sel[k], nm)) * rD;

    // output: idx = i*16 + k ; k2 = i/44 (k-independent)
    int n  = r / (S_FR - 1);
    int sp = r - n * (S_FR - 1);
    int k2 = i / 44;
    int im = i - k2 * 44;
    float4* o = reinterpret_cast<float4*>(
        out + ((size_t)((n * TOPK + k2) * (S_FR - 1) + sp)) * HW + im * 16);
    o[0] = make_float4(v[0],  v[1],  v[2],  v[3]);
    o[1] = make_float4(v[4],  v[5],  v[6],  v[7]);
    o[2] = make_float4(v[8],  v[9],  v[10], v[11]);
    o[3] = make_float4(v[12], v[13], v[14], v[15]);
}

// ---------------------------------------------------------------------------
extern "C" void kernel_launch(void* const* d_in, const int* in_sizes, int n_in,
                              void* d_out, int out_size) {
    const float* x  = (const float*)d_in[0];
    const float* w1 = (const float*)d_in[1];
    const float* b1 = (const float*)d_in[2];
    const float* w2 = (const float*)d_in[3];
    const float* b2 = (const float*)d_in[4];
    float* out = (float*)d_out;

    kA<<<NPIX / 64, 128>>>(x, w1, b1, w2, b2);
    kC<<<NS * 11, 64>>>(out);
}

// round 16
// speedup vs baseline: 1.3462x; 1.2040x over previous
#include <cuda_runtime.h>
#include <math_constants.h>

// Problem constants
#define N_BATCH 4
#define C_CH    128
#define S_FR    31
#define HW      704           // 32*22
#define NS      120           // 4*(31-1)
#define NPIX    87296         // 4*31*704 (= 64*1364)
#define TOPK    16
#define NB      64            // denominator bins
#define NWARP   22            // 704/32
#define LOG2E   1.4426950408889634f
#define LN2F    0.6931471805599453f

// Scratch (device globals — no allocation allowed)
__device__ float  g_X0[NS * HW];        // a values
__device__ float  g_BL[NS * HW];        // b * log2e (order-preserving)
__device__ float  g_TB[NS * 32];        // [0..15] top desc, [16..31] bottom asc
__device__ float4 g_BINS[NS * NB];      // (S0, S1, S2/2, S3/6)
__device__ float2 g_ROW[NS];            // (lo, W)

__device__ __forceinline__ float ex2(float x) {
    float r;
    asm("ex2.approx.f32 %0, %1;" : "=f"(r) : "f"(x));
    return r;
}

// ---------------------------------------------------------------------------
// Kernel A (R3 winner, verbatim): channel contraction, 2 threads per pixel.
// ---------------------------------------------------------------------------
__global__ void kA(const float* __restrict__ x,
                   const float* __restrict__ w1, const float* __restrict__ b1,
                   const float* __restrict__ w2, const float* __restrict__ b2) {
    __shared__ float sw1[C_CH], sw2[C_CH];
    __shared__ float r1s[64], r2s[64];
    int tid = threadIdx.x;          // 0..127
    sw1[tid] = w1[tid];
    sw2[tid] = w2[tid];
    __syncthreads();

    int half = tid >> 6;            // 0 or 1
    int px   = tid & 63;
    int p = blockIdx.x * 64 + px;   // NPIX = 64*1364 exactly
    int n = p / (S_FR * HW);
    int q = p - n * (S_FR * HW);
    int f = q / HW;
    int i = q - f * HW;

    const float* xp = x + (size_t)n * (C_CH * S_FR * HW)
                        + (size_t)(half * 64) * (S_FR * HW) + q;
    const float* pw1 = sw1 + half * 64;
    const float* pw2 = sw2 + half * 64;

    float y1a = 0.f, y1b = 0.f, y2a = 0.f, y2b = 0.f;
#pragma unroll
    for (int cb = 0; cb < 64; cb += 16) {
        float v[16];
#pragma unroll
        for (int u = 0; u < 16; u++) v[u] = xp[(cb + u) * (S_FR * HW)];
#pragma unroll
        for (int u = 0; u < 16; u += 2) {
            y1a = fmaf(v[u],     pw1[cb + u],     y1a);
            y2a = fmaf(v[u],     pw2[cb + u],     y2a);
            y1b = fmaf(v[u + 1], pw1[cb + u + 1], y1b);
            y2b = fmaf(v[u + 1], pw2[cb + u + 1], y2b);
        }
    }
    float y1 = y1a + y1b, y2 = y2a + y2b;

    if (half == 1) { r1s[px] = y1; r2s[px] = y2; }
    __syncthreads();
    if (half == 0) {
        y1 += r1s[px];
        y2 += r2s[px];
        if (f < S_FR - 1) g_X0[(n * (S_FR - 1) + f) * HW + i] = y1 + b1[0];
        if (f >= 1)       g_BL[(n * (S_FR - 1) + f - 1) * HW + i] = (y2 + b2[0]) * LOG2E;
    }
}

// ---------------------------------------------------------------------------
// Kernel B (R10, verbatim): per-row summary.
// ---------------------------------------------------------------------------
__global__ void __launch_bounds__(HW)
kB() {
    __shared__ float sv[HW], sv2[HW];
    __shared__ float binS0[NB], binS1[NB], binS2[NB], binS3[NB];
    __shared__ float rmin[NWARP], rmax[NWARP];
    __shared__ float s_lo, s_W;
    __shared__ int   s_ttop, s_tbot, s_fbtop, s_fbbot;
    __shared__ int   s_ctop, s_cbot;
    __shared__ float candT[40], candB[40];

    int r = blockIdx.x;
    int tid = threadIdx.x;   // 0..703
    int lane = tid & 31, wid = tid >> 5;

    float bv = g_BL[r * HW + tid];
    sv[tid] = bv; sv2[tid] = bv;
    if (tid < NB) { binS0[tid] = 0.f; binS1[tid] = 0.f; binS2[tid] = 0.f; binS3[tid] = 0.f; }
    if (tid == HW - 1) { s_ctop = 0; s_cbot = 0; }

    float lmin = bv, lmax = bv;
#pragma unroll
    for (int o = 16; o; o >>= 1) {
        lmin = fminf(lmin, __shfl_xor_sync(0xffffffffu, lmin, o));
        lmax = fmaxf(lmax, __shfl_xor_sync(0xffffffffu, lmax, o));
    }
    if (lane == 0) { rmin[wid] = lmin; rmax[wid] = lmax; }
    __syncthreads();
    if (tid == 0) {
        float lo = rmin[0], hi = rmax[0];
#pragma unroll
        for (int w = 1; w < NWARP; w++) { lo = fminf(lo, rmin[w]); hi = fmaxf(hi, rmax[w]); }
        s_lo = lo;
        s_W  = (hi - lo) * (1.0f / NB) + 1e-30f;
        g_ROW[r] = make_float2(lo, s_W);
    }
    __syncthreads();

    float lo = s_lo, W = s_W, invW = 1.0f / W;
    int m;
    {
        m = (int)((bv - lo) * invW);
        m = (m > NB - 1) ? NB - 1 : (m < 0 ? 0 : m);
        float d = bv - fmaf((float)m + 0.5f, W, lo);
        atomicAdd(&binS0[m], 1.0f);
        atomicAdd(&binS1[m], d);
        atomicAdd(&binS2[m], 0.5f * d * d);
        atomicAdd(&binS3[m], (1.0f / 6.0f) * d * d * d);
    }
    __syncthreads();

    // thresholds (lane owns bins 2l, 2l+1)
    if (wid == 0) {
        float c0 = binS0[2 * lane];
        float c1 = binS0[2 * lane + 1];
        float suf = c0 + c1;
#pragma unroll
        for (int o = 1; o < 32; o <<= 1) {
            float v = __shfl_down_sync(0xffffffffu, suf, o);
            if (lane + o < 32) suf += v;
        }
        float Seven = suf;              // suffix from bin 2l
        float Sodd  = suf - c0;         // suffix from bin 2l+1
        int best = -1;
        if (Sodd  >= 16.f) best = 2 * lane + 1;
        else if (Seven >= 16.f) best = 2 * lane;
        float Sb = (best == 2 * lane + 1) ? Sodd : ((best == 2 * lane) ? Seven : 0.f);
#pragma unroll
        for (int o = 16; o; o >>= 1) {
            int   ob = __shfl_xor_sync(0xffffffffu, best, o);
            float os = __shfl_xor_sync(0xffffffffu, Sb, o);
            if (ob > best) { best = ob; Sb = os; }
        }
        if (lane == 0) { s_ttop = best; s_fbtop = (Sb > 32.f) ? 1 : 0; }
    } else if (wid == 1) {
        float c0 = binS0[2 * lane];
        float c1 = binS0[2 * lane + 1];
        float pre = c0 + c1;
#pragma unroll
        for (int o = 1; o < 32; o <<= 1) {
            float v = __shfl_up_sync(0xffffffffu, pre, o);
            if (lane >= o) pre += v;
        }
        float Podd  = pre;              // prefix through bin 2l+1
        float Peven = pre - c1;         // prefix through bin 2l
        int best = 0x7fffffff;
        if (Peven >= 16.f) best = 2 * lane;
        else if (Podd >= 16.f) best = 2 * lane + 1;
        float Pb = (best == 2 * lane) ? Peven : ((best == 2 * lane + 1) ? Podd : 0.f);
#pragma unroll
        for (int o = 16; o; o >>= 1) {
            int   ob = __shfl_xor_sync(0xffffffffu, best, o);
            float os = __shfl_xor_sync(0xffffffffu, Pb, o);
            if (ob < best) { best = ob; Pb = os; }
        }
        if (lane == 0) { s_tbot = best; s_fbbot = (Pb > 32.f) ? 1 : 0; }
    }
    __syncthreads();

    if (!s_fbtop && m >= s_ttop) candT[atomicAdd(&s_ctop, 1)] = bv;
    if (!s_fbbot && m <= s_tbot) candB[atomicAdd(&s_cbot, 1)] = bv;
    // write bins while gather settles
    if (tid < NB)
        g_BINS[r * NB + tid] = make_float4(binS0[tid], binS1[tid], binS2[tid], binS3[tid]);
    __syncthreads();

    if (wid == 0) {
        if (!s_fbtop) {
            float v = (lane < s_ctop) ? candT[lane] : -CUDART_INF_F;
#pragma unroll
            for (int k = 2; k <= 32; k <<= 1) {
#pragma unroll
                for (int j = k >> 1; j > 0; j >>= 1) {
                    float o = __shfl_xor_sync(0xffffffffu, v, j);
                    bool up = ((lane & k) == 0);
                    bool keepMin = (((lane & j) == 0) == up);
                    v = keepMin ? fminf(v, o) : fmaxf(v, o);
                }
            }
            if (lane >= 16) g_TB[r * 32 + (31 - lane)] = v;   // top-16 desc
        } else {
            for (int it = 0; it < TOPK; it++) {
                float lm = -CUDART_INF_F; int li = 0;
                for (int j = lane; j < HW; j += 32) {
                    float v = sv[j];
                    if (v > lm) { lm = v; li = j; }
                }
#pragma unroll
                for (int o = 16; o; o >>= 1) {
                    float ov = __shfl_xor_sync(0xffffffffu, lm, o);
                    int   oi = __shfl_xor_sync(0xffffffffu, li, o);
                    if (ov > lm || (ov == lm && oi < li)) { lm = ov; li = oi; }
                }
                if (lane == 0) { g_TB[r * 32 + it] = lm; sv[li] = -CUDART_INF_F; }
                __syncwarp();
            }
        }
    } else if (wid == 1) {
        if (!s_fbbot) {
            float v = (lane < s_cbot) ? candB[lane] : CUDART_INF_F;
#pragma unroll
            for (int k = 2; k <= 32; k <<= 1) {
#pragma unroll
                for (int j = k >> 1; j > 0; j >>= 1) {
                    float o = __shfl_xor_sync(0xffffffffu, v, j);
                    bool up = ((lane & k) == 0);
                    bool keepMin = (((lane & j) == 0) == up);
                    v = keepMin ? fminf(v, o) : fmaxf(v, o);
                }
            }
            if (lane < 16) g_TB[r * 32 + 16 + lane] = v;      // bottom-16 asc
        } else {
            for (int it = 0; it < TOPK; it++) {
                float lm = CUDART_INF_F; int li = 0;
                for (int j = lane; j < HW; j += 32) {
                    float v = sv2[j];
                    if (v < lm) { lm = v; li = j; }
                }
#pragma unroll
                for (int o = 16; o; o >>= 1) {
                    float ov = __shfl_xor_sync(0xffffffffu, lm, o);
                    int   oi = __shfl_xor_sync(0xffffffffu, li, o);
                    if (ov < lm || (ov == lm && oi < li)) { lm = ov; li = oi; }
                }
                if (lane == 0) { g_TB[r * 32 + 16 + it] = lm; sv2[li] = CUDART_INF_F; }
                __syncwarp();
            }
        }
    }
}

// ---------------------------------------------------------------------------
// Kernel C: lane-pair emit. 1320 blocks x 128 threads; adjacent lanes 2k,2k+1
// share pixel k: each computes 32 of 64 bins, combine D via shfl_xor(1),
// each emits 8 of 16 numerators (2 of 4 STG.128).
// ---------------------------------------------------------------------------
__global__ void __launch_bounds__(128)
kC(float* __restrict__ out) {
    __shared__ float4 sb[NB];
    __shared__ float  ssel[32];
    __shared__ float2 srow;
    int r = blockIdx.x / 11;
    int chunk = blockIdx.x - r * 11;
    int tid = threadIdx.x;   // 0..127

    if (tid < NB) sb[tid] = g_BINS[r * NB + tid];
    else if (tid < NB + 32) ssel[tid - NB] = g_TB[r * 32 + (tid - NB)];
    else if (tid == 127) srow = g_ROW[r];
    __syncthreads();

    int px = tid >> 1;              // 0..63
    int h  = tid & 1;               // bin-half
    int i  = chunk * 64 + px;
    float a  = g_X0[r * HW + i];
    float lo = srow.x, W = srow.y;

    bool  pos  = (a >= 0.f);
    float u    = a * W;
    float mref = pos ? (float)(NB - 1) : 0.f;
    float cs   = fmaf(mref + 0.5f, W, lo);     // dominant bin center
    float L    = a * LN2F;
    float g1   = ex2(u);
    float g2   = g1 * g1;
    float g3   = g2 * g1;
    float g4   = g2 * g2;

    float D0 = 0.f, D1 = 0.f, D2 = 0.f, D3 = 0.f;
    int base = h * 32;
#pragma unroll
    for (int gg = 0; gg < 32; gg += 8) {
        int grp = base + gg;
        float pr = ex2(u * ((float)grp - mref));
        float q0 = pr, q1 = pr * g1, q2 = pr * g2, q3 = pr * g3;
        float4 c0 = sb[grp + 0];
        float4 c1 = sb[grp + 1];
        float4 c2 = sb[grp + 2];
        float4 c3 = sb[grp + 3];
        D0 = fmaf(q0, fmaf(L, fmaf(L, fmaf(L, c0.w, c0.z), c0.y), c0.x), D0);
        D1 = fmaf(q1, fmaf(L, fmaf(L, fmaf(L, c1.w, c1.z), c1.y), c1.x), D1);
        D2 = fmaf(q2, fmaf(L, fmaf(L, fmaf(L, c2.w, c2.z), c2.y), c2.x), D2);
        D3 = fmaf(q3, fmaf(L, fmaf(L, fmaf(L, c3.w, c3.z), c3.y), c3.x), D3);
        q0 *= g4; q1 *= g4; q2 *= g4; q3 *= g4;
        float4 c4 = sb[grp + 4];
        float4 c5 = sb[grp + 5];
        float4 c6 = sb[grp + 6];
        float4 c7 = sb[grp + 7];
        D0 = fmaf(q0, fmaf(L, fmaf(L, fmaf(L, c4.w, c4.z), c4.y), c4.x), D0);
        D1 = fmaf(q1, fmaf(L, fmaf(L, fmaf(L, c5.w, c5.z), c5.y), c5.x), D1);
        D2 = fmaf(q2, fmaf(L, fmaf(L, fmaf(L, c6.w, c6.z), c6.y), c6.x), D2);
        D3 = fmaf(q3, fmaf(L, fmaf(L, fmaf(L, c7.w, c7.z), c7.y), c7.x), D3);
    }
    float D = (D0 + D1) + (D2 + D3);
    D += __shfl_xor_sync(0xffffffffu, D, 1);   // pair combine -> full Dref

    float nm = -a * cs;
    float rD = __frcp_rn(D);
    const float* sel = (pos ? ssel : (ssel + 16)) + h * 8;
    float v[8];
#pragma unroll
    for (int k = 0; k < 8; k++)
        v[k] = ex2(fmaf(a, sel[k], nm)) * rD;

    // output: idx = i*16 + k ; k2 = i/44 (k-independent); this lane owns
    // the h-th half of the 16 -> float4 slots 2h, 2h+1.
    int n  = r / (S_FR - 1);
    int sp = r - n * (S_FR - 1);
    int k2 = i / 44;
    int im = i - k2 * 44;
    float4* o = reinterpret_cast<float4*>(
        out + ((size_t)((n * TOPK + k2) * (S_FR - 1) + sp)) * HW + im * 16) + h * 2;
    o[0] = make_float4(v[0], v[1], v[2], v[3]);
    o[1] = make_float4(v[4], v[5], v[6], v[7]);
}

// ---------------------------------------------------------------------------
extern "C" void kernel_launch(void* const* d_in, const int* in_sizes, int n_in,
                              void* d_out, int out_size) {
    const float* x  = (const float*)d_in[0];
    const float* w1 = (const float*)d_in[1];
    const float* b1 = (const float*)d_in[2];
    const float* w2 = (const float*)d_in[3];
    const float* b2 = (const float*)d_in[4];
    float* out = (float*)d_out;

    kA<<<NPIX / 64, 128>>>(x, w1, b1, w2, b2);
    kB<<<NS, HW>>>();
    kC<<<NS * 11, 128>>>(out);
}